// round 12
// baseline (speedup 1.0000x reference)
#include <cuda_runtime.h>
#include <cstdint>
#include <cstddef>

// ---------------------------------------------------------------------------
// FeatureFusionKAN:
//   attention = sigmoid([f1|f2] @ attn_w^T + b)            GEMM1 (K=2048)
//   kan_in    = [f1*att | f2*(1-att)]
//   h     = [silu(kan_in)|bspl(kan_in)] @ W0 (K=18432)     GEMM2
//   out   = [silu(h)     |bspl(h)    ] @ W1 (K=9216)       GEMM3
// All GEMMs: M=8192, N=1024. TF32 mma.sync with RNA-rounded operands,
// fp32 accumulate.
// ---------------------------------------------------------------------------

#define BATCH   8192
#define FEATN   1024
#define KATTN   2048
#define KL0     18432
#define KL1     9216

// ------------------------- device scratch (no allocs) ----------------------
__device__ float g_Acomb [(size_t)BATCH * KATTN];   //  64 MB
__device__ float g_Wattn [(size_t)FEATN * KATTN];   //   8 MB
__device__ float g_logits[(size_t)BATCH * FEATN];   //  32 MB
__device__ float g_W0    [(size_t)FEATN * KL0];     //  72 MB
__device__ float g_Xe0   [(size_t)BATCH * KL0];     // 576 MB
__device__ float g_h     [(size_t)BATCH * FEATN];   //  32 MB
__device__ float g_W1    [(size_t)FEATN * KL1];     //  36 MB
__device__ float g_Xe1   [(size_t)BATCH * KL1];     // 288 MB

// ------------------------------ helpers ------------------------------------
__device__ __forceinline__ float rna_tf32(float f) {
    uint32_t u;
    asm("cvt.rna.tf32.f32 %0, %1;" : "=r"(u) : "f"(f));
    return __uint_as_float(u);
}

__device__ __forceinline__ float sigmoidf_(float z) {
    return 1.0f / (1.0f + expf(-z));
}

// Cox-de Boor, order 3, uniform extended grid g_j = -1 + (j-3)*0.4, j=0..11.
// Produces the 8 cubic basis values. Matches the reference recursion.
__device__ __forceinline__ void bspline8(float x, float bb[8]) {
    const float h = 0.4f;
    float b[11];
#pragma unroll
    for (int j = 0; j < 11; ++j) {
        float g0 = -1.0f + (float)(j - 3) * h;
        float g1 = -1.0f + (float)(j - 2) * h;
        b[j] = (x >= g0 && x < g1) ? 1.0f : 0.0f;
    }
#pragma unroll
    for (int k = 1; k <= 3; ++k) {
        float invkh = 1.0f / ((float)k * h);
#pragma unroll
        for (int j = 0; j < 11 - k; ++j) {
            float gj   = -1.0f + (float)(j - 3) * h;
            float gjk1 = -1.0f + (float)(j + k - 2) * h;
            float left  = (x - gj)   * invkh;
            float right = (gjk1 - x) * invkh;
            b[j] = left * b[j] + right * b[j + 1];
        }
    }
#pragma unroll
    for (int i = 0; i < 8; ++i) bb[i] = b[i];
}

// ------------------------------ prep kernels -------------------------------
// A for attention GEMM: [f1|f2] RNA-rounded. 8192 x 2048.
__global__ void k_concat_round(const float* __restrict__ f1,
                               const float* __restrict__ f2,
                               float* __restrict__ dst) {
    int idx = blockIdx.x * blockDim.x + threadIdx.x;
    if (idx >= BATCH * KATTN) return;
    int b = idx >> 11;           // /2048
    int j = idx & 2047;
    float v = (j < FEATN) ? f1[b * FEATN + j] : f2[b * FEATN + (j - FEATN)];
    dst[idx] = rna_tf32(v);
}

__global__ void k_round_copy(const float* __restrict__ src,
                             float* __restrict__ dst, int n) {
    int idx = blockIdx.x * blockDim.x + threadIdx.x;
    if (idx < n) dst[idx] = rna_tf32(src[idx]);
}

// Assemble W = [base_w ; spline_w reshaped], layout [N][Ktot] (K contiguous),
// RNA-rounded. spline_w is (N, in, 8) row-major so the (in*8) tail is already
// contiguous per output row.
__global__ void k_pack_w(const float* __restrict__ basew,
                         const float* __restrict__ splinew,
                         float* __restrict__ dst,
                         int kbase, int ktot) {
    int idx = blockIdx.x * blockDim.x + threadIdx.x;
    int total = FEATN * ktot;
    if (idx >= total) return;
    int n = idx / ktot;
    int k = idx - n * ktot;
    float v = (k < kbase) ? basew[(size_t)n * kbase + k]
                          : splinew[(size_t)n * (ktot - kbase) + (k - kbase)];
    dst[idx] = rna_tf32(v);
}

// Expansion for layer 0: consumes attn logits, emits Xe0 row =
// [ silu(kan_in)[0..2047] | for i: B_0..B_7(kan_in[i]) ]  (18432 floats).
__global__ void k_build_xe0(const float* __restrict__ f1,
                            const float* __restrict__ f2,
                            const float* __restrict__ logits,
                            const float* __restrict__ bias,
                            float* __restrict__ xe) {
    int b = blockIdx.y;
    int j = blockIdx.x * blockDim.x + threadIdx.x;  // 0..2047
    if (j >= KATTN) return;
    int f = j & (FEATN - 1);
    float att = sigmoidf_(logits[(size_t)b * FEATN + f] + bias[f]);
    float x = (j < FEATN) ? f1[(size_t)b * FEATN + j] * att
                          : f2[(size_t)b * FEATN + f] * (1.0f - att);
    size_t base = (size_t)b * KL0;
    xe[base + j] = rna_tf32(x * sigmoidf_(x));   // silu
    float bb[8];
    bspline8(x, bb);
    float4 v0 = make_float4(rna_tf32(bb[0]), rna_tf32(bb[1]),
                            rna_tf32(bb[2]), rna_tf32(bb[3]));
    float4 v1 = make_float4(rna_tf32(bb[4]), rna_tf32(bb[5]),
                            rna_tf32(bb[6]), rna_tf32(bb[7]));
    float4* p = (float4*)(xe + base + KATTN + (size_t)j * 8);
    p[0] = v0;
    p[1] = v1;
}

// Expansion for layer 1 (in = 1024, Ktot = 9216).
__global__ void k_build_xe1(const float* __restrict__ h,
                            float* __restrict__ xe) {
    int b = blockIdx.y;
    int j = blockIdx.x * blockDim.x + threadIdx.x;  // 0..1023
    if (j >= FEATN) return;
    float x = h[(size_t)b * FEATN + j];
    size_t base = (size_t)b * KL1;
    xe[base + j] = rna_tf32(x * sigmoidf_(x));
    float bb[8];
    bspline8(x, bb);
    float4 v0 = make_float4(rna_tf32(bb[0]), rna_tf32(bb[1]),
                            rna_tf32(bb[2]), rna_tf32(bb[3]));
    float4 v1 = make_float4(rna_tf32(bb[4]), rna_tf32(bb[5]),
                            rna_tf32(bb[6]), rna_tf32(bb[7]));
    float4* p = (float4*)(xe + base + FEATN + (size_t)j * 8);
    p[0] = v0;
    p[1] = v1;
}

// ------------------------------- GEMM --------------------------------------
// C[M,N] = A[M,K] (row-major) * B^T where B stored [N][K] (K contiguous).
// TF32 mma.sync m16n8k8, fp32 accumulate. CTA tile 128x128, BK=16,
// 8 warps (4x2), warp tile 32x64. 2-stage cp.async pipeline.
#define GT_M 128
#define GT_N 128
#define GT_K 16
#define GSTRIDE 20   // BK + 4 pad -> conflict-free LDS, rows stay 16B aligned

__device__ __forceinline__ void cp_async16(void* smem, const void* gmem) {
    uint32_t s = (uint32_t)__cvta_generic_to_shared(smem);
    asm volatile("cp.async.cg.shared.global [%0], [%1], 16;\n" ::
                 "r"(s), "l"(gmem));
}

__device__ __forceinline__ void mma_tf32(float c[4], const uint32_t a[4],
                                         const uint32_t b[2]) {
    asm volatile(
        "mma.sync.aligned.m16n8k8.row.col.f32.tf32.tf32.f32 "
        "{%0,%1,%2,%3}, {%4,%5,%6,%7}, {%8,%9}, {%0,%1,%2,%3};\n"
        : "+f"(c[0]), "+f"(c[1]), "+f"(c[2]), "+f"(c[3])
        : "r"(a[0]), "r"(a[1]), "r"(a[2]), "r"(a[3]),
          "r"(b[0]), "r"(b[1]));
}

__global__ void __launch_bounds__(256, 2)
k_gemm_tf32(const float* __restrict__ A, const float* __restrict__ B,
            float* __restrict__ C, int M, int N, int K) {
    __shared__ __align__(16) float As[2][GT_M][GSTRIDE];
    __shared__ __align__(16) float Bs[2][GT_N][GSTRIDE];

    const int tid  = threadIdx.x;
    const int lane = tid & 31;
    const int wid  = tid >> 5;
    const int wm   = wid & 3;   // warp row   (0..3) -> 32 M-rows each
    const int wn   = wid >> 2;  // warp col   (0..1) -> 64 N-cols each
    const int g    = lane >> 2; // group id 0..7
    const int t4   = lane & 3;  // thread-in-group 0..3

    const int mBase = blockIdx.y * GT_M;
    const int nBase = blockIdx.x * GT_N;

    // loader mapping: 512 float4 per tile, 2 per thread (rows r and r+64)
    const int ldRow = tid >> 2;          // 0..63
    const int ldC4  = (tid & 3) * 4;     // 0,4,8,12
    const float* Aptr = A + (size_t)(mBase + ldRow) * K + ldC4;
    const float* Bptr = B + (size_t)(nBase + ldRow) * K + ldC4;

    float acc[2][8][4];
#pragma unroll
    for (int mt = 0; mt < 2; ++mt)
#pragma unroll
        for (int nt = 0; nt < 8; ++nt)
#pragma unroll
            for (int i = 0; i < 4; ++i) acc[mt][nt][i] = 0.0f;

    const int numK = K / GT_K;

    // prologue: stage 0
    cp_async16(&As[0][ldRow][ldC4],      Aptr);
    cp_async16(&As[0][ldRow + 64][ldC4], Aptr + (size_t)64 * K);
    cp_async16(&Bs[0][ldRow][ldC4],      Bptr);
    cp_async16(&Bs[0][ldRow + 64][ldC4], Bptr + (size_t)64 * K);
    asm volatile("cp.async.commit_group;\n");

    for (int kt = 0; kt < numK; ++kt) {
        asm volatile("cp.async.wait_group 0;\n");
        __syncthreads();
        const int st = kt & 1;

        if (kt + 1 < numK) {
            const int ns = st ^ 1;
            const int ko = (kt + 1) * GT_K;
            cp_async16(&As[ns][ldRow][ldC4],      Aptr + ko);
            cp_async16(&As[ns][ldRow + 64][ldC4], Aptr + (size_t)64 * K + ko);
            cp_async16(&Bs[ns][ldRow][ldC4],      Bptr + ko);
            cp_async16(&Bs[ns][ldRow + 64][ldC4], Bptr + (size_t)64 * K + ko);
            asm volatile("cp.async.commit_group;\n");
        }

#pragma unroll
        for (int kk = 0; kk < GT_K; kk += 8) {
            uint32_t a[2][4];
#pragma unroll
            for (int mt = 0; mt < 2; ++mt) {
                const int r = wm * 32 + mt * 16;
                a[mt][0] = __float_as_uint(As[st][r + g][kk + t4]);
                a[mt][1] = __float_as_uint(As[st][r + g + 8][kk + t4]);
                a[mt][2] = __float_as_uint(As[st][r + g][kk + t4 + 4]);
                a[mt][3] = __float_as_uint(As[st][r + g + 8][kk + t4 + 4]);
            }
            uint32_t b[8][2];
#pragma unroll
            for (int nt = 0; nt < 8; ++nt) {
                const int c = wn * 64 + nt * 8;
                b[nt][0] = __float_as_uint(Bs[st][c + g][kk + t4]);
                b[nt][1] = __float_as_uint(Bs[st][c + g][kk + t4 + 4]);
            }
#pragma unroll
            for (int mt = 0; mt < 2; ++mt)
#pragma unroll
                for (int nt = 0; nt < 8; ++nt)
                    mma_tf32(acc[mt][nt], a[mt], b[nt]);
        }
        __syncthreads();
    }

    // epilogue
#pragma unroll
    for (int mt = 0; mt < 2; ++mt) {
#pragma unroll
        for (int nt = 0; nt < 8; ++nt) {
            const int r = mBase + wm * 32 + mt * 16 + g;
            const int c = nBase + wn * 64 + nt * 8 + 2 * t4;
            float2* p0 = (float2*)(C + (size_t)r * N + c);
            *p0 = make_float2(acc[mt][nt][0], acc[mt][nt][1]);
            float2* p1 = (float2*)(C + (size_t)(r + 8) * N + c);
            *p1 = make_float2(acc[mt][nt][2], acc[mt][nt][3]);
        }
    }
}

// ------------------------------ launch --------------------------------------
extern "C" void kernel_launch(void* const* d_in, const int* in_sizes, int n_in,
                              void* d_out, int out_size) {
    const float* feat1     = (const float*)d_in[0];
    const float* feat2     = (const float*)d_in[1];
    const float* attn_w    = (const float*)d_in[2];
    const float* attn_b    = (const float*)d_in[3];
    const float* base_w0   = (const float*)d_in[4];
    const float* spline_w0 = (const float*)d_in[5];
    const float* base_w1   = (const float*)d_in[6];
    const float* spline_w1 = (const float*)d_in[7];
    float* out = (float*)d_out;

    float *Acomb, *Wattn, *logits, *W0, *Xe0, *h, *W1, *Xe1;
    cudaGetSymbolAddress((void**)&Acomb,  g_Acomb);
    cudaGetSymbolAddress((void**)&Wattn,  g_Wattn);
    cudaGetSymbolAddress((void**)&logits, g_logits);
    cudaGetSymbolAddress((void**)&W0,     g_W0);
    cudaGetSymbolAddress((void**)&Xe0,    g_Xe0);
    cudaGetSymbolAddress((void**)&h,      g_h);
    cudaGetSymbolAddress((void**)&W1,     g_W1);
    cudaGetSymbolAddress((void**)&Xe1,    g_Xe1);

    const dim3 gemmGrid(FEATN / GT_N, BATCH / GT_M);  // (8, 64)

    // weight prep (independent of activations)
    {
        int n = FEATN * KATTN;
        k_round_copy<<<(n + 255) / 256, 256>>>(attn_w, Wattn, n);
    }
    {
        int n = FEATN * KL0;
        k_pack_w<<<(n + 255) / 256, 256>>>(base_w0, spline_w0, W0, KATTN, KL0);
    }
    {
        int n = FEATN * KL1;
        k_pack_w<<<(n + 255) / 256, 256>>>(base_w1, spline_w1, W1, FEATN, KL1);
    }

    // attention GEMM
    {
        int n = BATCH * KATTN;
        k_concat_round<<<(n + 255) / 256, 256>>>(feat1, feat2, Acomb);
    }
    k_gemm_tf32<<<gemmGrid, 256>>>(Acomb, Wattn, logits, BATCH, FEATN, KATTN);

    // layer 0
    k_build_xe0<<<dim3(KATTN / 256, BATCH), 256>>>(feat1, feat2, logits,
                                                   attn_b, Xe0);
    k_gemm_tf32<<<gemmGrid, 256>>>(Xe0, W0, h, BATCH, FEATN, KL0);

    // layer 1
    k_build_xe1<<<dim3(FEATN / 256, BATCH), 256>>>(h, Xe1);
    k_gemm_tf32<<<gemmGrid, 256>>>(Xe1, W1, out, BATCH, FEATN, KL1);
}

// round 15
// speedup vs baseline: 1.1092x; 1.1092x over previous
#include <cuda_runtime.h>
#include <cstdint>
#include <cstddef>

// ---------------------------------------------------------------------------
// FeatureFusionKAN on GB300 (sm_103, non-'a' virtual arch => no tcgen05):
//   attention = sigmoid([f1|f2] @ attn_w^T + b)            GEMM1 (K=2048)
//   kan_in    = [f1*att | f2*(1-att)]
//   h     = [silu(kan_in)|bspl(kan_in)] @ W0 (K=18432)     GEMM2
//   out   = [silu(h)     |bspl(h)    ] @ W1 (K=9216)       GEMM3
// GEMMs: TF32 mma.sync m16n8k8, fp32 accumulate. 128x128 CTA tile,
// 4 warps @ 64x64 warp tiles (2x crossbar margin vs HMMA), BK=16,
// 3-stage cp.async pipeline, one barrier per K-iter.
// ---------------------------------------------------------------------------

#define BATCH   8192
#define FEATN   1024
#define KATTN   2048
#define KL0     18432
#define KL1     9216

// ------------------------- device scratch (no allocs) ----------------------
__device__ float g_Acomb [(size_t)BATCH * KATTN];   //  64 MB
__device__ float g_Wattn [(size_t)FEATN * KATTN];   //   8 MB
__device__ float g_logits[(size_t)BATCH * FEATN];   //  32 MB
__device__ float g_W0    [(size_t)FEATN * KL0];     //  72 MB
__device__ float g_Xe0   [(size_t)BATCH * KL0];     // 576 MB
__device__ float g_h     [(size_t)BATCH * FEATN];   //  32 MB
__device__ float g_W1    [(size_t)FEATN * KL1];     //  36 MB
__device__ float g_Xe1   [(size_t)BATCH * KL1];     // 288 MB

// ------------------------------ helpers ------------------------------------
__device__ __forceinline__ float rna_tf32(float f) {
    uint32_t u;
    asm("cvt.rna.tf32.f32 %0, %1;" : "=r"(u) : "f"(f));
    return __uint_as_float(u);
}

__device__ __forceinline__ float sigmoidf_(float z) {
    return 1.0f / (1.0f + expf(-z));
}

// Cox-de Boor, order 3, uniform extended grid g_j = -1 + (j-3)*0.4, j=0..11.
__device__ __forceinline__ void bspline8(float x, float bb[8]) {
    const float h = 0.4f;
    float b[11];
#pragma unroll
    for (int j = 0; j < 11; ++j) {
        float g0 = -1.0f + (float)(j - 3) * h;
        float g1 = -1.0f + (float)(j - 2) * h;
        b[j] = (x >= g0 && x < g1) ? 1.0f : 0.0f;
    }
#pragma unroll
    for (int k = 1; k <= 3; ++k) {
        float invkh = 1.0f / ((float)k * h);
#pragma unroll
        for (int j = 0; j < 11 - k; ++j) {
            float gj   = -1.0f + (float)(j - 3) * h;
            float gjk1 = -1.0f + (float)(j + k - 2) * h;
            float left  = (x - gj)   * invkh;
            float right = (gjk1 - x) * invkh;
            b[j] = left * b[j] + right * b[j + 1];
        }
    }
#pragma unroll
    for (int i = 0; i < 8; ++i) bb[i] = b[i];
}

// ------------------------------ prep kernels -------------------------------
__global__ void k_concat_round(const float* __restrict__ f1,
                               const float* __restrict__ f2,
                               float* __restrict__ dst) {
    int idx = blockIdx.x * blockDim.x + threadIdx.x;
    if (idx >= BATCH * KATTN) return;
    int b = idx >> 11;
    int j = idx & 2047;
    float v = (j < FEATN) ? f1[b * FEATN + j] : f2[b * FEATN + (j - FEATN)];
    dst[idx] = rna_tf32(v);
}

__global__ void k_round_copy(const float* __restrict__ src,
                             float* __restrict__ dst, int n) {
    int idx = blockIdx.x * blockDim.x + threadIdx.x;
    if (idx < n) dst[idx] = rna_tf32(src[idx]);
}

__global__ void k_pack_w(const float* __restrict__ basew,
                         const float* __restrict__ splinew,
                         float* __restrict__ dst,
                         int kbase, int ktot) {
    int idx = blockIdx.x * blockDim.x + threadIdx.x;
    int total = FEATN * ktot;
    if (idx >= total) return;
    int n = idx / ktot;
    int k = idx - n * ktot;
    float v = (k < kbase) ? basew[(size_t)n * kbase + k]
                          : splinew[(size_t)n * (ktot - kbase) + (k - kbase)];
    dst[idx] = rna_tf32(v);
}

__global__ void k_build_xe0(const float* __restrict__ f1,
                            const float* __restrict__ f2,
                            const float* __restrict__ logits,
                            const float* __restrict__ bias,
                            float* __restrict__ xe) {
    int b = blockIdx.y;
    int j = blockIdx.x * blockDim.x + threadIdx.x;
    if (j >= KATTN) return;
    int f = j & (FEATN - 1);
    float att = sigmoidf_(logits[(size_t)b * FEATN + f] + bias[f]);
    float x = (j < FEATN) ? f1[(size_t)b * FEATN + j] * att
                          : f2[(size_t)b * FEATN + f] * (1.0f - att);
    size_t base = (size_t)b * KL0;
    xe[base + j] = rna_tf32(x * sigmoidf_(x));
    float bb[8];
    bspline8(x, bb);
    float4 v0 = make_float4(rna_tf32(bb[0]), rna_tf32(bb[1]),
                            rna_tf32(bb[2]), rna_tf32(bb[3]));
    float4 v1 = make_float4(rna_tf32(bb[4]), rna_tf32(bb[5]),
                            rna_tf32(bb[6]), rna_tf32(bb[7]));
    float4* p = (float4*)(xe + base + KATTN + (size_t)j * 8);
    p[0] = v0;
    p[1] = v1;
}

__global__ void k_build_xe1(const float* __restrict__ h,
                            float* __restrict__ xe) {
    int b = blockIdx.y;
    int j = blockIdx.x * blockDim.x + threadIdx.x;
    if (j >= FEATN) return;
    float x = h[(size_t)b * FEATN + j];
    size_t base = (size_t)b * KL1;
    xe[base + j] = rna_tf32(x * sigmoidf_(x));
    float bb[8];
    bspline8(x, bb);
    float4 v0 = make_float4(rna_tf32(bb[0]), rna_tf32(bb[1]),
                            rna_tf32(bb[2]), rna_tf32(bb[3]));
    float4 v1 = make_float4(rna_tf32(bb[4]), rna_tf32(bb[5]),
                            rna_tf32(bb[6]), rna_tf32(bb[7]));
    float4* p = (float4*)(xe + base + FEATN + (size_t)j * 8);
    p[0] = v0;
    p[1] = v1;
}

// ------------------------------- GEMM --------------------------------------
// C[M,N] = A[M,K] (row-major) * B^T where B stored [N][K] (K contiguous).
// TF32 mma.sync m16n8k8, fp32 accumulate. CTA tile 128x128, BK=16,
// 4 warps (2x2), warp tile 64x64, 3-stage cp.async pipeline, dynamic smem.
#define GT_M     128
#define GT_N     128
#define GT_K     16
#define GSTRIDE  20            // BK + 4 pad: conflict-free LDS, rows 16B-aligned
#define GT_S     3             // pipeline stages
#define STG_F    (GT_M * GSTRIDE * 2)          // floats per stage (A+B)
#define GT_SMEM  (GT_S * STG_F * 4)            // 61440 bytes

__device__ __forceinline__ void cp_async16(void* smem, const void* gmem) {
    uint32_t s = (uint32_t)__cvta_generic_to_shared(smem);
    asm volatile("cp.async.cg.shared.global [%0], [%1], 16;\n" ::
                 "r"(s), "l"(gmem));
}

__device__ __forceinline__ void mma_tf32(float c[4], const uint32_t a[4],
                                         const uint32_t b[2]) {
    asm volatile(
        "mma.sync.aligned.m16n8k8.row.col.f32.tf32.tf32.f32 "
        "{%0,%1,%2,%3}, {%4,%5,%6,%7}, {%8,%9}, {%0,%1,%2,%3};\n"
        : "+f"(c[0]), "+f"(c[1]), "+f"(c[2]), "+f"(c[3])
        : "r"(a[0]), "r"(a[1]), "r"(a[2]), "r"(a[3]),
          "r"(b[0]), "r"(b[1]));
}

__global__ void __launch_bounds__(128, 2)
k_gemm_tf32(const float* __restrict__ A, const float* __restrict__ B,
            float* __restrict__ C, int M, int N, int K) {
    extern __shared__ float Ss[];   // [GT_S][2][128][GSTRIDE]: A then B per stage

    const int tid  = threadIdx.x;
    const int lane = tid & 31;
    const int wid  = tid >> 5;
    const int wm   = wid & 1;   // warp row (0..1) -> 64 M-rows
    const int wn   = wid >> 1;  // warp col (0..1) -> 64 N-cols
    const int g    = lane >> 2; // group id 0..7
    const int t4   = lane & 3;  // thread-in-group 0..3

    const int mBase = blockIdx.y * GT_M;
    const int nBase = blockIdx.x * GT_N;
    const int numK  = K / GT_K;

    // loader mapping: 512 float4 per matrix per stage; 128 thr x 4 rows each
    const int ldRow = tid >> 2;          // 0..31 (then +32,+64,+96)
    const int ldC4  = (tid & 3) * 4;     // 0,4,8,12
    const float* Aptr = A + (size_t)(mBase + ldRow) * K + ldC4;
    const float* Bptr = B + (size_t)(nBase + ldRow) * K + ldC4;

    float acc[4][8][4];
#pragma unroll
    for (int mt = 0; mt < 4; ++mt)
#pragma unroll
        for (int nt = 0; nt < 8; ++nt)
#pragma unroll
            for (int i = 0; i < 4; ++i) acc[mt][nt][i] = 0.0f;

    // ---- prologue: stages 0..GT_S-2 ----
#pragma unroll
    for (int t = 0; t < GT_S - 1; ++t) {
        float* sa = Ss + t * STG_F;
        float* sb = sa + GT_M * GSTRIDE;
        const size_t ko = (size_t)t * GT_K;
#pragma unroll
        for (int i = 0; i < 4; ++i) {
            cp_async16(sa + (ldRow + 32 * i) * GSTRIDE + ldC4,
                       Aptr + (size_t)(32 * i) * K + ko);
            cp_async16(sb + (ldRow + 32 * i) * GSTRIDE + ldC4,
                       Bptr + (size_t)(32 * i) * K + ko);
        }
        asm volatile("cp.async.commit_group;\n");
    }

    int stC = 0;            // slot of tile kt
    int stL = GT_S - 1;     // slot of tile kt + GT_S - 1
    for (int kt = 0; kt < numK; ++kt) {
        asm volatile("cp.async.wait_group %0;\n" :: "n"(GT_S - 2));
        __syncthreads();

        // refill: tile kt + GT_S - 1 into slot stL
        {
            int tl = kt + GT_S - 1;
            if (tl < numK) {
                float* sa = Ss + stL * STG_F;
                float* sb = sa + GT_M * GSTRIDE;
                const size_t ko = (size_t)tl * GT_K;
#pragma unroll
                for (int i = 0; i < 4; ++i) {
                    cp_async16(sa + (ldRow + 32 * i) * GSTRIDE + ldC4,
                               Aptr + (size_t)(32 * i) * K + ko);
                    cp_async16(sb + (ldRow + 32 * i) * GSTRIDE + ldC4,
                               Bptr + (size_t)(32 * i) * K + ko);
                }
            }
            asm volatile("cp.async.commit_group;\n");
        }

        // compute on slot stC
        const float* sa = Ss + stC * STG_F;
        const float* sb = sa + GT_M * GSTRIDE;
#pragma unroll
        for (int kk = 0; kk < GT_K; kk += 8) {
            uint32_t a[4][4];
#pragma unroll
            for (int mt = 0; mt < 4; ++mt) {
                const int r = wm * 64 + mt * 16;
                a[mt][0] = __float_as_uint(sa[(r + g)     * GSTRIDE + kk + t4]);
                a[mt][1] = __float_as_uint(sa[(r + g + 8) * GSTRIDE + kk + t4]);
                a[mt][2] = __float_as_uint(sa[(r + g)     * GSTRIDE + kk + t4 + 4]);
                a[mt][3] = __float_as_uint(sa[(r + g + 8) * GSTRIDE + kk + t4 + 4]);
            }
            uint32_t b[8][2];
#pragma unroll
            for (int nt = 0; nt < 8; ++nt) {
                const int c = wn * 64 + nt * 8;
                b[nt][0] = __float_as_uint(sb[(c + g) * GSTRIDE + kk + t4]);
                b[nt][1] = __float_as_uint(sb[(c + g) * GSTRIDE + kk + t4 + 4]);
            }
#pragma unroll
            for (int mt = 0; mt < 4; ++mt)
#pragma unroll
                for (int nt = 0; nt < 8; ++nt)
                    mma_tf32(acc[mt][nt], a[mt], b[nt]);
        }

        if (++stC == GT_S) stC = 0;
        if (++stL == GT_S) stL = 0;
    }

    // epilogue
#pragma unroll
    for (int mt = 0; mt < 4; ++mt) {
#pragma unroll
        for (int nt = 0; nt < 8; ++nt) {
            const int r = mBase + wm * 64 + mt * 16 + g;
            const int c = nBase + wn * 64 + nt * 8 + 2 * t4;
            float2* p0 = (float2*)(C + (size_t)r * N + c);
            *p0 = make_float2(acc[mt][nt][0], acc[mt][nt][1]);
            float2* p1 = (float2*)(C + (size_t)(r + 8) * N + c);
            *p1 = make_float2(acc[mt][nt][2], acc[mt][nt][3]);
        }
    }
}

// ------------------------------ launch --------------------------------------
extern "C" void kernel_launch(void* const* d_in, const int* in_sizes, int n_in,
                              void* d_out, int out_size) {
    const float* feat1     = (const float*)d_in[0];
    const float* feat2     = (const float*)d_in[1];
    const float* attn_w    = (const float*)d_in[2];
    const float* attn_b    = (const float*)d_in[3];
    const float* base_w0   = (const float*)d_in[4];
    const float* spline_w0 = (const float*)d_in[5];
    const float* base_w1   = (const float*)d_in[6];
    const float* spline_w1 = (const float*)d_in[7];
    float* out = (float*)d_out;

    float *Acomb, *Wattn, *logits, *W0, *Xe0, *h, *W1, *Xe1;
    cudaGetSymbolAddress((void**)&Acomb,  g_Acomb);
    cudaGetSymbolAddress((void**)&Wattn,  g_Wattn);
    cudaGetSymbolAddress((void**)&logits, g_logits);
    cudaGetSymbolAddress((void**)&W0,     g_W0);
    cudaGetSymbolAddress((void**)&Xe0,    g_Xe0);
    cudaGetSymbolAddress((void**)&h,      g_h);
    cudaGetSymbolAddress((void**)&W1,     g_W1);
    cudaGetSymbolAddress((void**)&Xe1,    g_Xe1);

    cudaFuncSetAttribute(k_gemm_tf32,
                         cudaFuncAttributeMaxDynamicSharedMemorySize, GT_SMEM);

    const dim3 gemmGrid(FEATN / GT_N, BATCH / GT_M);  // (8, 64)

    // weight prep (independent of activations)
    {
        int n = FEATN * KATTN;
        k_round_copy<<<(n + 255) / 256, 256>>>(attn_w, Wattn, n);
    }
    {
        int n = FEATN * KL0;
        k_pack_w<<<(n + 255) / 256, 256>>>(base_w0, spline_w0, W0, KATTN, KL0);
    }
    {
        int n = FEATN * KL1;
        k_pack_w<<<(n + 255) / 256, 256>>>(base_w1, spline_w1, W1, FEATN, KL1);
    }

    // attention GEMM
    {
        int n = BATCH * KATTN;
        k_concat_round<<<(n + 255) / 256, 256>>>(feat1, feat2, Acomb);
    }
    k_gemm_tf32<<<gemmGrid, 128, GT_SMEM>>>(Acomb, Wattn, logits,
                                            BATCH, FEATN, KATTN);

    // layer 0
    k_build_xe0<<<dim3(KATTN / 256, BATCH), 256>>>(feat1, feat2, logits,
                                                   attn_b, Xe0);
    k_gemm_tf32<<<gemmGrid, 128, GT_SMEM>>>(Xe0, W0, h, BATCH, FEATN, KL0);

    // layer 1
    k_build_xe1<<<dim3(FEATN / 256, BATCH), 256>>>(h, Xe1);
    k_gemm_tf32<<<gemmGrid, 128, GT_SMEM>>>(Xe1, W1, out, BATCH, FEATN, KL1);
}

// round 16
// speedup vs baseline: 1.9975x; 1.8008x over previous
#include <cuda_runtime.h>
#include <cuda_fp16.h>
#include <cstdint>
#include <cstddef>

// ---------------------------------------------------------------------------
// FeatureFusionKAN on GB300 (sm_103 non-'a' => legacy mma.sync only):
//   attention = sigmoid([f1|f2] @ attn_w^T + b)            GEMM1 (K=2048)
//   kan_in    = [f1*att | f2*(1-att)]
//   h     = [silu(kan_in)|bspl(kan_in)] @ W0 (K=18432)     GEMM2
//   out   = [silu(h)     |bspl(h)    ] @ W1 (K=9216)       GEMM3
// GEMMs: FP16 mma.sync m16n8k16 (same 10-bit mantissa as tf32, 2x rate),
// fp32 accumulate. 128x128 CTA tile, 4 warps @ 64x64, BK=32 fp16,
// 3-stage cp.async pipeline.
// ---------------------------------------------------------------------------

#define BATCH   8192
#define FEATN   1024
#define KATTN   2048
#define KL0     18432
#define KL1     9216

// ------------------------- device scratch (no allocs) ----------------------
__device__ __half g_Acomb [(size_t)BATCH * KATTN];   //  32 MB
__device__ __half g_Wattn [(size_t)FEATN * KATTN];   //   4 MB
__device__ float  g_logits[(size_t)BATCH * FEATN];   //  32 MB
__device__ __half g_W0    [(size_t)FEATN * KL0];     //  36 MB
__device__ __half g_Xe0   [(size_t)BATCH * KL0];     // 288 MB
__device__ float  g_h     [(size_t)BATCH * FEATN];   //  32 MB
__device__ __half g_W1    [(size_t)FEATN * KL1];     //  18 MB
__device__ __half g_Xe1   [(size_t)BATCH * KL1];     // 144 MB

// ------------------------------ helpers ------------------------------------
__device__ __forceinline__ float sigmoidf_(float z) {
    return 1.0f / (1.0f + expf(-z));
}

// Cox-de Boor, order 3, uniform extended grid g_j = -1 + (j-3)*0.4, j=0..11.
__device__ __forceinline__ void bspline8(float x, float bb[8]) {
    const float h = 0.4f;
    float b[11];
#pragma unroll
    for (int j = 0; j < 11; ++j) {
        float g0 = -1.0f + (float)(j - 3) * h;
        float g1 = -1.0f + (float)(j - 2) * h;
        b[j] = (x >= g0 && x < g1) ? 1.0f : 0.0f;
    }
#pragma unroll
    for (int k = 1; k <= 3; ++k) {
        float invkh = 1.0f / ((float)k * h);
#pragma unroll
        for (int j = 0; j < 11 - k; ++j) {
            float gj   = -1.0f + (float)(j - 3) * h;
            float gjk1 = -1.0f + (float)(j + k - 2) * h;
            float left  = (x - gj)   * invkh;
            float right = (gjk1 - x) * invkh;
            b[j] = left * b[j] + right * b[j + 1];
        }
    }
#pragma unroll
    for (int i = 0; i < 8; ++i) bb[i] = b[i];
}

// ------------------------------ prep kernels -------------------------------
__global__ void k_concat_half(const float* __restrict__ f1,
                              const float* __restrict__ f2,
                              __half* __restrict__ dst) {
    int idx = blockIdx.x * blockDim.x + threadIdx.x;
    if (idx >= BATCH * KATTN) return;
    int b = idx >> 11;
    int j = idx & 2047;
    float v = (j < FEATN) ? f1[b * FEATN + j] : f2[b * FEATN + (j - FEATN)];
    dst[idx] = __float2half_rn(v);
}

__global__ void k_half_copy(const float* __restrict__ src,
                            __half* __restrict__ dst, int n) {
    int idx = blockIdx.x * blockDim.x + threadIdx.x;
    if (idx < n) dst[idx] = __float2half_rn(src[idx]);
}

__global__ void k_pack_w(const float* __restrict__ basew,
                         const float* __restrict__ splinew,
                         __half* __restrict__ dst,
                         int kbase, int ktot) {
    int idx = blockIdx.x * blockDim.x + threadIdx.x;
    int total = FEATN * ktot;
    if (idx >= total) return;
    int n = idx / ktot;
    int k = idx - n * ktot;
    float v = (k < kbase) ? basew[(size_t)n * kbase + k]
                          : splinew[(size_t)n * (ktot - kbase) + (k - kbase)];
    dst[idx] = __float2half_rn(v);
}

__global__ void k_build_xe0(const float* __restrict__ f1,
                            const float* __restrict__ f2,
                            const float* __restrict__ logits,
                            const float* __restrict__ bias,
                            __half* __restrict__ xe) {
    int b = blockIdx.y;
    int j = blockIdx.x * blockDim.x + threadIdx.x;
    if (j >= KATTN) return;
    int f = j & (FEATN - 1);
    float att = sigmoidf_(logits[(size_t)b * FEATN + f] + bias[f]);
    float x = (j < FEATN) ? f1[(size_t)b * FEATN + j] * att
                          : f2[(size_t)b * FEATN + f] * (1.0f - att);
    size_t base = (size_t)b * KL0;
    xe[base + j] = __float2half_rn(x * sigmoidf_(x));
    float bb[8];
    bspline8(x, bb);
    __align__(16) __half hb[8];
#pragma unroll
    for (int i = 0; i < 8; ++i) hb[i] = __float2half_rn(bb[i]);
    *(uint4*)(xe + base + KATTN + (size_t)j * 8) = *(const uint4*)hb;
}

__global__ void k_build_xe1(const float* __restrict__ h,
                            __half* __restrict__ xe) {
    int b = blockIdx.y;
    int j = blockIdx.x * blockDim.x + threadIdx.x;
    if (j >= FEATN) return;
    float x = h[(size_t)b * FEATN + j];
    size_t base = (size_t)b * KL1;
    xe[base + j] = __float2half_rn(x * sigmoidf_(x));
    float bb[8];
    bspline8(x, bb);
    __align__(16) __half hb[8];
#pragma unroll
    for (int i = 0; i < 8; ++i) hb[i] = __float2half_rn(bb[i]);
    *(uint4*)(xe + base + FEATN + (size_t)j * 8) = *(const uint4*)hb;
}

// ------------------------------- GEMM --------------------------------------
// C[M,N] = A[M,K] (row-major fp16) * B^T, B stored [N][K] (K contiguous fp16).
// FP16 mma.sync m16n8k16, fp32 accumulate. CTA tile 128x128, BK=32 fp16,
// 4 warps (2x2), warp tile 64x64, 3-stage cp.async pipeline, dynamic smem.
#define GT_M     128
#define GT_N     128
#define GT_BK    32            // fp16 per K-chunk (64 bytes/row)
#define HSTRIDE  40            // fp16 per smem row (32 + 8 pad = 80 B)
#define GT_S     3             // pipeline stages
#define STG_H    (GT_M * HSTRIDE * 2)          // fp16 per stage (A+B) = 10240
#define GT_SMEM  (GT_S * STG_H * 2)            // 61440 bytes

__device__ __forceinline__ void cp_async16(void* smem, const void* gmem) {
    uint32_t s = (uint32_t)__cvta_generic_to_shared(smem);
    asm volatile("cp.async.cg.shared.global [%0], [%1], 16;\n" ::
                 "r"(s), "l"(gmem));
}

__device__ __forceinline__ uint32_t ld32h(const __half* p) {
    return *reinterpret_cast<const uint32_t*>(p);
}

__device__ __forceinline__ void mma_f16(float c[4], const uint32_t a[4],
                                        const uint32_t b[2]) {
    asm volatile(
        "mma.sync.aligned.m16n8k16.row.col.f32.f16.f16.f32 "
        "{%0,%1,%2,%3}, {%4,%5,%6,%7}, {%8,%9}, {%0,%1,%2,%3};\n"
        : "+f"(c[0]), "+f"(c[1]), "+f"(c[2]), "+f"(c[3])
        : "r"(a[0]), "r"(a[1]), "r"(a[2]), "r"(a[3]),
          "r"(b[0]), "r"(b[1]));
}

__global__ void __launch_bounds__(128, 2)
k_gemm_f16(const __half* __restrict__ A, const __half* __restrict__ B,
           float* __restrict__ C, int M, int N, int K) {
    extern __shared__ __half Hs[];  // [GT_S][A:128*40 | B:128*40]

    const int tid  = threadIdx.x;
    const int lane = tid & 31;
    const int wid  = tid >> 5;
    const int wm   = wid & 1;   // warp row (0..1) -> 64 M-rows
    const int wn   = wid >> 1;  // warp col (0..1) -> 64 N-cols
    const int g    = lane >> 2; // group id 0..7
    const int t4   = lane & 3;  // thread-in-group 0..3

    const int mBase = blockIdx.y * GT_M;
    const int nBase = blockIdx.x * GT_N;
    const int numK  = K / GT_BK;

    // loader: per stage, A = 128 rows x 64 B = 512 x 16B chunks; same for B.
    // 128 threads x 4 row-passes x (1 A-chunk + 1 B-chunk).
    const int ldRow = tid >> 2;          // 0..31 (then +32,+64,+96)
    const int ldC   = (tid & 3) * 8;     // fp16 offset: 0,8,16,24 (16B chunks)
    const __half* Aptr = A + (size_t)(mBase + ldRow) * K + ldC;
    const __half* Bptr = B + (size_t)(nBase + ldRow) * K + ldC;

    float acc[4][8][4];
#pragma unroll
    for (int mt = 0; mt < 4; ++mt)
#pragma unroll
        for (int nt = 0; nt < 8; ++nt)
#pragma unroll
            for (int i = 0; i < 4; ++i) acc[mt][nt][i] = 0.0f;

    // ---- prologue: stages 0..GT_S-2 ----
#pragma unroll
    for (int t = 0; t < GT_S - 1; ++t) {
        __half* sa = Hs + t * STG_H;
        __half* sb = sa + GT_M * HSTRIDE;
        const size_t ko = (size_t)t * GT_BK;
#pragma unroll
        for (int i = 0; i < 4; ++i) {
            cp_async16(sa + (ldRow + 32 * i) * HSTRIDE + ldC,
                       Aptr + (size_t)(32 * i) * K + ko);
            cp_async16(sb + (ldRow + 32 * i) * HSTRIDE + ldC,
                       Bptr + (size_t)(32 * i) * K + ko);
        }
        asm volatile("cp.async.commit_group;\n");
    }

    int stC = 0;            // slot of tile kt
    int stL = GT_S - 1;     // slot of tile kt + GT_S - 1
    for (int kt = 0; kt < numK; ++kt) {
        asm volatile("cp.async.wait_group %0;\n" :: "n"(GT_S - 2));
        __syncthreads();

        // refill tile kt + GT_S - 1 into slot stL
        {
            int tl = kt + GT_S - 1;
            if (tl < numK) {
                __half* sa = Hs + stL * STG_H;
                __half* sb = sa + GT_M * HSTRIDE;
                const size_t ko = (size_t)tl * GT_BK;
#pragma unroll
                for (int i = 0; i < 4; ++i) {
                    cp_async16(sa + (ldRow + 32 * i) * HSTRIDE + ldC,
                               Aptr + (size_t)(32 * i) * K + ko);
                    cp_async16(sb + (ldRow + 32 * i) * HSTRIDE + ldC,
                               Bptr + (size_t)(32 * i) * K + ko);
                }
            }
            asm volatile("cp.async.commit_group;\n");
        }

        // compute on slot stC: 2 k-steps of k=16
        const __half* sa = Hs + stC * STG_H;
        const __half* sb = sa + GT_M * HSTRIDE;
#pragma unroll
        for (int ks = 0; ks < 2; ++ks) {
            const int kk = ks * 16;
            uint32_t a[4][4];
#pragma unroll
            for (int mt = 0; mt < 4; ++mt) {
                const int r = wm * 64 + mt * 16;
                a[mt][0] = ld32h(sa + (r + g)     * HSTRIDE + kk + 2 * t4);
                a[mt][1] = ld32h(sa + (r + g + 8) * HSTRIDE + kk + 2 * t4);
                a[mt][2] = ld32h(sa + (r + g)     * HSTRIDE + kk + 8 + 2 * t4);
                a[mt][3] = ld32h(sa + (r + g + 8) * HSTRIDE + kk + 8 + 2 * t4);
            }
            uint32_t b[8][2];
#pragma unroll
            for (int nt = 0; nt < 8; ++nt) {
                const int c = wn * 64 + nt * 8;
                b[nt][0] = ld32h(sb + (c + g) * HSTRIDE + kk + 2 * t4);
                b[nt][1] = ld32h(sb + (c + g) * HSTRIDE + kk + 8 + 2 * t4);
            }
#pragma unroll
            for (int mt = 0; mt < 4; ++mt)
#pragma unroll
                for (int nt = 0; nt < 8; ++nt)
                    mma_f16(acc[mt][nt], a[mt], b[nt]);
        }

        if (++stC == GT_S) stC = 0;
        if (++stL == GT_S) stL = 0;
    }

    // epilogue
#pragma unroll
    for (int mt = 0; mt < 4; ++mt) {
#pragma unroll
        for (int nt = 0; nt < 8; ++nt) {
            const int r = mBase + wm * 64 + mt * 16 + g;
            const int c = nBase + wn * 64 + nt * 8 + 2 * t4;
            float2* p0 = (float2*)(C + (size_t)r * N + c);
            *p0 = make_float2(acc[mt][nt][0], acc[mt][nt][1]);
            float2* p1 = (float2*)(C + (size_t)(r + 8) * N + c);
            *p1 = make_float2(acc[mt][nt][2], acc[mt][nt][3]);
        }
    }
}

// ------------------------------ launch --------------------------------------
extern "C" void kernel_launch(void* const* d_in, const int* in_sizes, int n_in,
                              void* d_out, int out_size) {
    const float* feat1     = (const float*)d_in[0];
    const float* feat2     = (const float*)d_in[1];
    const float* attn_w    = (const float*)d_in[2];
    const float* attn_b    = (const float*)d_in[3];
    const float* base_w0   = (const float*)d_in[4];
    const float* spline_w0 = (const float*)d_in[5];
    const float* base_w1   = (const float*)d_in[6];
    const float* spline_w1 = (const float*)d_in[7];
    float* out = (float*)d_out;

    __half *Acomb, *Wattn, *W0, *Xe0, *W1, *Xe1;
    float *logits, *h;
    cudaGetSymbolAddress((void**)&Acomb,  g_Acomb);
    cudaGetSymbolAddress((void**)&Wattn,  g_Wattn);
    cudaGetSymbolAddress((void**)&logits, g_logits);
    cudaGetSymbolAddress((void**)&W0,     g_W0);
    cudaGetSymbolAddress((void**)&Xe0,    g_Xe0);
    cudaGetSymbolAddress((void**)&h,      g_h);
    cudaGetSymbolAddress((void**)&W1,     g_W1);
    cudaGetSymbolAddress((void**)&Xe1,    g_Xe1);

    cudaFuncSetAttribute(k_gemm_f16,
                         cudaFuncAttributeMaxDynamicSharedMemorySize, GT_SMEM);

    const dim3 gemmGrid(FEATN / GT_N, BATCH / GT_M);  // (8, 64)

    // weight prep (independent of activations)
    {
        int n = FEATN * KATTN;
        k_half_copy<<<(n + 255) / 256, 256>>>(attn_w, Wattn, n);
    }
    {
        int n = FEATN * KL0;
        k_pack_w<<<(n + 255) / 256, 256>>>(base_w0, spline_w0, W0, KATTN, KL0);
    }
    {
        int n = FEATN * KL1;
        k_pack_w<<<(n + 255) / 256, 256>>>(base_w1, spline_w1, W1, FEATN, KL1);
    }

    // attention GEMM
    {
        int n = BATCH * KATTN;
        k_concat_half<<<(n + 255) / 256, 256>>>(feat1, feat2, Acomb);
    }
    k_gemm_f16<<<gemmGrid, 128, GT_SMEM>>>(Acomb, Wattn, logits,
                                           BATCH, FEATN, KATTN);

    // layer 0
    k_build_xe0<<<dim3(KATTN / 256, BATCH), 256>>>(feat1, feat2, logits,
                                                   attn_b, Xe0);
    k_gemm_f16<<<gemmGrid, 128, GT_SMEM>>>(Xe0, W0, h, BATCH, FEATN, KL0);

    // layer 1
    k_build_xe1<<<dim3(FEATN / 256, BATCH), 256>>>(h, Xe1);
    k_gemm_f16<<<gemmGrid, 128, GT_SMEM>>>(Xe1, W1, out, BATCH, FEATN, KL1);
}